// round 10
// baseline (speedup 1.0000x reference)
#include <cuda_runtime.h>
#include <cuda_fp16.h>
#include <cstdint>

// Problem shape (fixed)
#define BB 16
#define CC 512
#define LL 4096

typedef __half hf;

// ---------------- Scratch (device globals; no allocation allowed) -----------
__device__ __align__(256) float g_kf[(size_t)BB * CC * LL];   // k pre-softmax fp32
__device__ __align__(256) hf g_xh[(size_t)BB * CC * LL];
__device__ __align__(256) hf g_qh[(size_t)BB * CC * LL];
__device__ __align__(256) hf g_ql[(size_t)BB * CC * LL];
__device__ __align__(256) hf g_vh[(size_t)BB * CC * LL];
__device__ __align__(256) hf g_vl[(size_t)BB * CC * LL];
__device__ __align__(256) hf g_kh[(size_t)BB * CC * LL];
__device__ __align__(256) hf g_ch[(size_t)BB * CC * CC];
__device__ __align__(256) hf g_cl[(size_t)BB * CC * CC];
__device__ __align__(256) hf g_mh[(size_t)BB * CC * CC];
__device__ __align__(256) hf g_wqh[3 * CC * CC];
__device__ __align__(256) hf g_woh[CC * CC];

// ---------------- PTX helpers ----------------
__device__ __forceinline__ uint32_t smem_u32(const void* p) {
    uint32_t a;
    asm("{ .reg .u64 t; cvta.to.shared.u64 t, %1; cvt.u32.u64 %0, t; }" : "=r"(a) : "l"(p));
    return a;
}
#define LDSM4(r0, r1, r2, r3, addr) \
    asm volatile("ldmatrix.sync.aligned.m8n8.x4.shared.b16 {%0,%1,%2,%3}, [%4];" \
                 : "=r"(r0), "=r"(r1), "=r"(r2), "=r"(r3) : "r"(addr))
#define LDSM4T(r0, r1, r2, r3, addr) \
    asm volatile("ldmatrix.sync.aligned.m8n8.x4.trans.shared.b16 {%0,%1,%2,%3}, [%4];" \
                 : "=r"(r0), "=r"(r1), "=r"(r2), "=r"(r3) : "r"(addr))
#define MMA16816(c, a, b) \
    asm volatile("mma.sync.aligned.m16n8k16.row.col.f32.f16.f16.f32 " \
                 "{%0,%1,%2,%3}, {%4,%5,%6,%7}, {%8,%9}, {%0,%1,%2,%3};" \
                 : "+f"((c)[0]), "+f"((c)[1]), "+f"((c)[2]), "+f"((c)[3]) \
                 : "r"((a)[0]), "r"((a)[1]), "r"((a)[2]), "r"((a)[3]), \
                   "r"((b)[0]), "r"((b)[1]))
#define CP16(dst, src) \
    asm volatile("cp.async.cg.shared.global [%0], [%1], 16;" :: "r"(dst), "l"(src))
#define CP_COMMIT() asm volatile("cp.async.commit_group;" ::: "memory")
#define CP_WAIT(n)  asm volatile("cp.async.wait_group %0;" :: "n"(n) : "memory")

__device__ __forceinline__ void split2h(float f0, float f1, uint32_t& hi, uint32_t& lo) {
    __half2 h = __float22half2_rn(make_float2(f0, f1));
    float r0 = f0 - __half2float(__low2half(h));
    float r1 = f1 - __half2float(__high2half(h));
    __half2 l = __float22half2_rn(make_float2(r0, r1));
    hi = *reinterpret_cast<uint32_t*>(&h);
    lo = *reinterpret_cast<uint32_t*>(&l);
}
__device__ __forceinline__ uint32_t pack2h(float f0, float f1) {
    __half2 h = __float22half2_rn(make_float2(f0, f1));
    return *reinterpret_cast<uint32_t*>(&h);
}

// ============================================================================
// wgemm: C[m,n] = sum_k A[m,k] * B'[k,n], fp16 HMMA.
//   NPASS=1: Ahi*Bhi only;  NPASS=2: Ahi*(Bhi+Blo)
//   B_IS_KN=true : B stored [K,N] (NN);  false: [N,K] (NT)
//   EPI: 0 = fp32 out (+bias), 1 = half hi/lo out, 2 = GEMM1 special
//        (third 0 -> q hi/lo, 1 -> k fp32, 2 -> v hi/lo), 3 = half hi only.
// Block tile 128x128, K-chunk 32, 4-stage cp.async ring, 256 thr
// (8 warps 2x4, warp tile 64x32), 2 CTAs/SM.
// ============================================================================
#define NSTAGE 4
#define STG_B  24576
#define WG_SMEM (NSTAGE * STG_B)   // 96 KB
#define P_AH 0
#define P_BH 8192
#define P_BL 16384

template <bool B_IS_KN, int NPASS, int EPI, bool ADD_BIAS>
__global__ __launch_bounds__(256, 2) void wgemm(
    const hf* __restrict__ Ah,
    const hf* __restrict__ Bh, const hf* __restrict__ Bl,
    float* __restrict__ Cf, hf* __restrict__ Ch, hf* __restrict__ Cl,
    hf* __restrict__ Ch2, hf* __restrict__ Cl2,
    const float* __restrict__ bias,
    int K, long sA, long sB, long sC, int lda, int ldb, int ldc)
{
    extern __shared__ char smem[];
    const uint32_t sb = smem_u32(smem);

    const int tid  = threadIdx.x;
    const int lane = tid & 31;
    const int wid  = tid >> 5;
    const int wm   = wid >> 2;          // 0..1
    const int wn   = wid & 3;           // 0..3
    const int m0 = blockIdx.y * 128;
    const int n0 = blockIdx.x * 128;
    const long z = blockIdx.z;

    Ah += z * sA + (long)m0 * lda;
    const long boff = z * sB + (B_IS_KN ? (long)n0 : (long)n0 * ldb);
    Bh += boff;
    if (NPASS == 2) Bl += boff;
    if (EPI == 0 || EPI == 2) Cf += z * sC;
    if (EPI == 1 || EPI == 2 || EPI == 3) Ch += z * sC;
    if (EPI == 1 || EPI == 2) Cl += z * sC;
    if (EPI == 2) { Ch2 += z * sC; Cl2 += z * sC; }

    const int ln15 = lane & 15;
    const int grp  = lane >> 4;
    const int sw64 = (ln15 >> 1) & 3;

    float acc[4][4][4];
    #pragma unroll
    for (int i = 0; i < 4; i++)
        #pragma unroll
        for (int j = 0; j < 4; j++)
            #pragma unroll
            for (int q = 0; q < 4; q++) acc[i][j][q] = 0.0f;

    // -------- cp.async stage fill --------
    auto issue = [&](int chunk, int s) {
        const int k0 = chunk * 32;
        const uint32_t st = sb + s * STG_B;
        // A plane: 128 rows x 64B, swizzle c ^ ((row>>1)&3); 2 segs/thread
        #pragma unroll
        for (int i = 0; i < 2; i++) {
            const int seg = tid + i * 256;
            const int row = seg >> 2;
            const int c   = seg & 3;
            const uint32_t doff = row * 64 + (((c ^ ((row >> 1) & 3)) & 3) << 4);
            CP16(st + P_AH + doff, Ah + (long)row * lda + k0 + c * 8);
        }
        if (!B_IS_KN) {
            // B planes: 128 rows x 64B; 2 segs/thread/plane
            #pragma unroll
            for (int i = 0; i < 2; i++) {
                const int seg = tid + i * 256;
                const int row = seg >> 2;
                const int c   = seg & 3;
                const uint32_t doff = row * 64 + (((c ^ ((row >> 1) & 3)) & 3) << 4);
                const long soff = (long)row * ldb + k0 + c * 8;
                CP16(st + P_BH + doff, Bh + soff);
                if (NPASS == 2) CP16(st + P_BL + doff, Bl + soff);
            }
        } else {
            // B planes: 32 k-rows x 256B, swizzle c ^ (k&7); 2 segs/thread/plane
            #pragma unroll
            for (int i = 0; i < 2; i++) {
                const int seg = tid + i * 256;
                const int k   = seg >> 4;
                const int c   = seg & 15;
                const uint32_t doff = k * 256 + (((c ^ (k & 7)) & 15) << 4);
                const long soff = (long)(k0 + k) * ldb + c * 8;
                CP16(st + P_BH + doff, Bh + soff);
                if (NPASS == 2) CP16(st + P_BL + doff, Bl + soff);
            }
        }
    };

    // -------- fragment loads --------
    int a_row_off[4];
    #pragma unroll
    for (int i = 0; i < 4; i++)
        a_row_off[i] = (wm * 64 + i * 16 + ln15) * 64;
    int b_row_off[2];
    #pragma unroll
    for (int jp = 0; jp < 2; jp++)
        b_row_off[jp] = (wn * 32 + jp * 16 + ln15) * 64;
    const int kn_k7 = ln15 & 7;

    auto lda_frags = [&](uint32_t plane, int ks, uint32_t af[4][4]) {
        const int c = ks * 2 + grp;
        #pragma unroll
        for (int i = 0; i < 4; i++) {
            uint32_t addr = plane + a_row_off[i] + (((c ^ sw64) & 3) << 4);
            LDSM4(af[i][0], af[i][1], af[i][2], af[i][3], addr);
        }
    };
    auto ldb_frags = [&](uint32_t plane, int ks, uint32_t bf[4][2]) {
        if (B_IS_KN) {
            const uint32_t krow = (uint32_t)(ks * 16 + ln15) << 8;
            #pragma unroll
            for (int jp = 0; jp < 2; jp++) {
                const int cn = wn * 4 + jp * 2 + grp;
                uint32_t addr = plane + krow + (((cn ^ kn_k7) & 15) << 4);
                uint32_t r0, r1, r2, r3;
                LDSM4T(r0, r1, r2, r3, addr);
                bf[jp * 2    ][0] = r0; bf[jp * 2    ][1] = r1;
                bf[jp * 2 + 1][0] = r2; bf[jp * 2 + 1][1] = r3;
            }
        } else {
            const int c = ks * 2 + grp;
            #pragma unroll
            for (int jp = 0; jp < 2; jp++) {
                uint32_t addr = plane + b_row_off[jp] + (((c ^ sw64) & 3) << 4);
                uint32_t r0, r1, r2, r3;
                LDSM4(r0, r1, r2, r3, addr);
                bf[jp * 2    ][0] = r0; bf[jp * 2    ][1] = r2;
                bf[jp * 2 + 1][0] = r1; bf[jp * 2 + 1][1] = r3;
            }
        }
    };
    auto mma_pass = [&](uint32_t af[4][4], uint32_t bf[4][2]) {
        #pragma unroll
        for (int i = 0; i < 4; i++)
            #pragma unroll
            for (int j = 0; j < 4; j++)
                MMA16816(acc[i][j], af[i], bf[j]);
    };
    auto compute_chunk = [&](int s) {
        const uint32_t base = sb + s * STG_B;
        #pragma unroll
        for (int ks = 0; ks < 2; ks++) {
            uint32_t ah[4][4];
            lda_frags(base + P_AH, ks, ah);
            {
                uint32_t bh[4][2];
                ldb_frags(base + P_BH, ks, bh);
                mma_pass(ah, bh);
            }
            if (NPASS == 2) {
                uint32_t bl[4][2];
                ldb_frags(base + P_BL, ks, bl);
                mma_pass(ah, bl);
            }
        }
    };

    // -------- multistage main loop --------
    const int NC = K >> 5;
    #pragma unroll
    for (int s = 0; s < NSTAGE - 1; s++) {
        if (s < NC) { issue(s, s); }
        CP_COMMIT();
    }
    for (int c = 0; c < NC; c++) {
        CP_WAIT(NSTAGE - 2);
        __syncthreads();
        const int pf = c + NSTAGE - 1;
        if (pf < NC) { issue(pf, pf & (NSTAGE - 1)); }
        CP_COMMIT();
        compute_chunk(c & (NSTAGE - 1));
    }

    // -------- epilogue --------
    #pragma unroll
    for (int i = 0; i < 4; i++) {
        const int row = m0 + wm * 64 + i * 16 + (lane >> 2);
        #pragma unroll
        for (int j = 0; j < 4; j++) {
            const int col = n0 + wn * 32 + j * 8 + (lane & 3) * 2;
            if (EPI == 0) {
                float bv0 = 0.0f, bv1 = 0.0f;
                if (ADD_BIAS) { bv0 = bias[row]; bv1 = bias[row + 8]; }
                float2 v0 = make_float2(acc[i][j][0] + bv0, acc[i][j][1] + bv0);
                float2 v1 = make_float2(acc[i][j][2] + bv1, acc[i][j][3] + bv1);
                *reinterpret_cast<float2*>(&Cf[(long)row * ldc + col])       = v0;
                *reinterpret_cast<float2*>(&Cf[(long)(row + 8) * ldc + col]) = v1;
            } else if (EPI == 1) {
                uint32_t h0, l0, h1, l1;
                split2h(acc[i][j][0], acc[i][j][1], h0, l0);
                split2h(acc[i][j][2], acc[i][j][3], h1, l1);
                *reinterpret_cast<uint32_t*>(&Ch[(long)row * ldc + col])       = h0;
                *reinterpret_cast<uint32_t*>(&Cl[(long)row * ldc + col])       = l0;
                *reinterpret_cast<uint32_t*>(&Ch[(long)(row + 8) * ldc + col]) = h1;
                *reinterpret_cast<uint32_t*>(&Cl[(long)(row + 8) * ldc + col]) = l1;
            } else if (EPI == 3) {
                *reinterpret_cast<uint32_t*>(&Ch[(long)row * ldc + col]) =
                    pack2h(acc[i][j][0], acc[i][j][1]);
                *reinterpret_cast<uint32_t*>(&Ch[(long)(row + 8) * ldc + col]) =
                    pack2h(acc[i][j][2], acc[i][j][3]);
            } else {
                const int third = blockIdx.y >> 2;      // 4 m-tiles of 128 per 512 rows
                const int lr = row & 511;
                if (third == 1) {
                    float2 v0 = make_float2(acc[i][j][0], acc[i][j][1]);
                    float2 v1 = make_float2(acc[i][j][2], acc[i][j][3]);
                    *reinterpret_cast<float2*>(&Cf[(long)lr * ldc + col])       = v0;
                    *reinterpret_cast<float2*>(&Cf[(long)(lr + 8) * ldc + col]) = v1;
                } else {
                    hf* dh = (third == 0) ? Ch : Ch2;
                    hf* dl = (third == 0) ? Cl : Cl2;
                    uint32_t h0, l0, h1, l1;
                    split2h(acc[i][j][0], acc[i][j][1], h0, l0);
                    split2h(acc[i][j][2], acc[i][j][3], h1, l1);
                    *reinterpret_cast<uint32_t*>(&dh[(long)lr * ldc + col])       = h0;
                    *reinterpret_cast<uint32_t*>(&dl[(long)lr * ldc + col])       = l0;
                    *reinterpret_cast<uint32_t*>(&dh[(long)(lr + 8) * ldc + col]) = h1;
                    *reinterpret_cast<uint32_t*>(&dl[(long)(lr + 8) * ldc + col]) = l1;
                }
            }
        }
    }
}

// ============================================================================
// split kernels: fp32 -> half hi(/lo)
// ============================================================================
__global__ __launch_bounds__(256) void split_arr(
    const float* __restrict__ s, hf* __restrict__ h, hf* __restrict__ l, long n)
{
    long i = ((long)blockIdx.x * 256 + threadIdx.x) * 4;
    if (i >= n) return;
    float4 v = *reinterpret_cast<const float4*>(s + i);
    uint32_t h0, l0, h1, l1;
    split2h(v.x, v.y, h0, l0);
    split2h(v.z, v.w, h1, l1);
    *reinterpret_cast<uint2*>(h + i) = make_uint2(h0, h1);
    *reinterpret_cast<uint2*>(l + i) = make_uint2(l0, l1);
}
__global__ __launch_bounds__(256) void split_hi(
    const float* __restrict__ s, hf* __restrict__ h, long n)
{
    long i = ((long)blockIdx.x * 256 + threadIdx.x) * 4;
    if (i >= n) return;
    float4 v = *reinterpret_cast<const float4*>(s + i);
    *reinterpret_cast<uint2*>(h + i) = make_uint2(pack2h(v.x, v.y), pack2h(v.z, v.w));
}

// ============================================================================
// softmax over L on kf fp32 -> half hi only
// ============================================================================
__global__ __launch_bounds__(256) void softmax_h(
    const float* __restrict__ kf, hf* __restrict__ kh)
{
    const int r = blockIdx.x;
    const int b = blockIdx.y;
    const long off = ((long)b * CC + r) * LL;
    const float* p = kf + off;
    const int tid = threadIdx.x;
    __shared__ float red[8];

    float v[16];
    float mx = -1e30f;
    #pragma unroll
    for (int i = 0; i < 16; i++) { v[i] = p[tid + i * 256]; mx = fmaxf(mx, v[i]); }
    #pragma unroll
    for (int o = 16; o > 0; o >>= 1) mx = fmaxf(mx, __shfl_xor_sync(0xffffffffu, mx, o));
    if ((tid & 31) == 0) red[tid >> 5] = mx;
    __syncthreads();
    if (tid < 32) {
        float m2 = (tid < 8) ? red[tid] : -1e30f;
        #pragma unroll
        for (int o = 4; o > 0; o >>= 1) m2 = fmaxf(m2, __shfl_xor_sync(0xffffffffu, m2, o));
        if (tid == 0) red[0] = m2;
    }
    __syncthreads();
    mx = red[0];
    __syncthreads();

    float s = 0.0f;
    #pragma unroll
    for (int i = 0; i < 16; i++) { v[i] = __expf(v[i] - mx); s += v[i]; }
    #pragma unroll
    for (int o = 16; o > 0; o >>= 1) s += __shfl_xor_sync(0xffffffffu, s, o);
    if ((tid & 31) == 0) red[tid >> 5] = s;
    __syncthreads();
    if (tid < 32) {
        float s2 = (tid < 8) ? red[tid] : 0.0f;
        #pragma unroll
        for (int o = 4; o > 0; o >>= 1) s2 += __shfl_xor_sync(0xffffffffu, s2, o);
        if (tid == 0) red[0] = s2;
    }
    __syncthreads();
    const float inv = 1.0f / red[0];

    #pragma unroll
    for (int i = 0; i < 16; i++)
        kh[off + tid + i * 256] = __float2half_rn(v[i] * inv);
}

// ============================================================================
extern "C" void kernel_launch(void* const* d_in, const int* in_sizes, int n_in,
                              void* d_out, int out_size)
{
    const float* x = nullptr; const float* w_qkv = nullptr;
    const float* w_out = nullptr; const float* b_out = nullptr;
    for (int i = 0; i < n_in; i++) {
        switch (in_sizes[i]) {
            case 33554432: x     = (const float*)d_in[i]; break;
            case 786432:   w_qkv = (const float*)d_in[i]; break;
            case 262144:   w_out = (const float*)d_in[i]; break;
            case 512:      b_out = (const float*)d_in[i]; break;
            default: break;
        }
    }
    float* y = (float*)d_out;

    float* kf;  cudaGetSymbolAddress((void**)&kf,  g_kf);
    hf *xh, *qh, *ql, *vh, *vl, *kh, *ch, *cl, *mh, *wqh, *woh;
    cudaGetSymbolAddress((void**)&xh, g_xh);
    cudaGetSymbolAddress((void**)&qh, g_qh);   cudaGetSymbolAddress((void**)&ql, g_ql);
    cudaGetSymbolAddress((void**)&vh, g_vh);   cudaGetSymbolAddress((void**)&vl, g_vl);
    cudaGetSymbolAddress((void**)&kh, g_kh);
    cudaGetSymbolAddress((void**)&ch, g_ch);   cudaGetSymbolAddress((void**)&cl, g_cl);
    cudaGetSymbolAddress((void**)&mh, g_mh);
    cudaGetSymbolAddress((void**)&wqh, g_wqh);
    cudaGetSymbolAddress((void**)&woh, g_woh);

    cudaFuncSetAttribute(wgemm<true,  1, 2, false>, cudaFuncAttributeMaxDynamicSharedMemorySize, WG_SMEM);
    cudaFuncSetAttribute(wgemm<false, 2, 1, false>, cudaFuncAttributeMaxDynamicSharedMemorySize, WG_SMEM);
    cudaFuncSetAttribute(wgemm<false, 2, 3, false>, cudaFuncAttributeMaxDynamicSharedMemorySize, WG_SMEM);
    cudaFuncSetAttribute(wgemm<true,  2, 0, true >, cudaFuncAttributeMaxDynamicSharedMemorySize, WG_SMEM);

    const long sBig = (long)CC * LL;
    const long sCtx = (long)CC * CC;

    // 0) pre-split inputs: everything hi only except v/q/ctx intermediates
    split_hi<<<(unsigned)((size_t)BB * CC * LL / 1024), 256>>>(x, xh, (long)BB * CC * LL);
    split_hi<<<3 * CC * CC / 1024, 256>>>(w_qkv, wqh, 3 * CC * CC);
    split_hi<<<CC * CC / 1024, 256>>>(w_out, woh, CC * CC);

    // 1) qkv = w_qkv @ x (NN, 1-pass): q -> hi/lo, k -> fp32, v -> hi/lo
    wgemm<true, 1, 2, false><<<dim3(LL / 128, (3 * CC) / 128, BB), 256, WG_SMEM>>>(
        wqh, xh, nullptr, kf, qh, ql, vh, vl, nullptr,
        CC, 0, sBig, sBig, CC, LL, LL);

    // 2) softmax over L on k -> hi
    softmax_h<<<dim3(CC, BB), 256>>>(kf, kh);

    // 3) ctx = k_sm @ v^T (NT, 2-pass) -> hi/lo
    wgemm<false, 2, 1, false><<<dim3(CC / 128, CC / 128, BB), 256, WG_SMEM>>>(
        kh, vh, vl, nullptr, ch, cl, nullptr, nullptr, nullptr,
        LL, sBig, sBig, sCtx, LL, LL, CC);

    // 4) M = w_out @ ctx^T (NT, 2-pass) -> hi only
    wgemm<false, 2, 3, false><<<dim3(CC / 128, CC / 128, BB), 256, WG_SMEM>>>(
        woh, ch, cl, nullptr, mh, nullptr, nullptr, nullptr, nullptr,
        CC, 0, sCtx, sCtx, CC, CC, CC);

    // 5) y = M @ q + b_out (NN, 2-pass, fp32 + bias)
    wgemm<true, 2, 0, true><<<dim3(LL / 128, CC / 128, BB), 256, WG_SMEM>>>(
        mh, qh, ql, y, nullptr, nullptr, nullptr, nullptr, b_out,
        CC, sCtx, sBig, sBig, CC, LL, LL);

    (void)out_size;
}

// round 11
// speedup vs baseline: 1.0022x; 1.0022x over previous
#include <cuda_runtime.h>
#include <cuda_fp16.h>
#include <cstdint>

// Problem shape (fixed)
#define BB 16
#define CC 512
#define LL 4096

typedef __half hf;

// ---------------- Scratch (device globals; no allocation allowed) -----------
__device__ __align__(256) float g_kf[(size_t)BB * CC * LL];   // k pre-softmax fp32
__device__ __align__(256) hf g_xh[(size_t)BB * CC * LL];
__device__ __align__(256) hf g_qh[(size_t)BB * CC * LL];
__device__ __align__(256) hf g_ql[(size_t)BB * CC * LL];
__device__ __align__(256) hf g_vh[(size_t)BB * CC * LL];
__device__ __align__(256) hf g_vl[(size_t)BB * CC * LL];
__device__ __align__(256) hf g_kh[(size_t)BB * CC * LL];
__device__ __align__(256) hf g_ch[(size_t)BB * CC * CC];
__device__ __align__(256) hf g_cl[(size_t)BB * CC * CC];
__device__ __align__(256) hf g_mh[(size_t)BB * CC * CC];
__device__ __align__(256) hf g_wqh[3 * CC * CC];
__device__ __align__(256) hf g_woh[CC * CC];

// ---------------- PTX helpers ----------------
__device__ __forceinline__ uint32_t smem_u32(const void* p) {
    uint32_t a;
    asm("{ .reg .u64 t; cvta.to.shared.u64 t, %1; cvt.u32.u64 %0, t; }" : "=r"(a) : "l"(p));
    return a;
}
#define LDSM4(r0, r1, r2, r3, addr) \
    asm volatile("ldmatrix.sync.aligned.m8n8.x4.shared.b16 {%0,%1,%2,%3}, [%4];" \
                 : "=r"(r0), "=r"(r1), "=r"(r2), "=r"(r3) : "r"(addr))
#define LDSM4T(r0, r1, r2, r3, addr) \
    asm volatile("ldmatrix.sync.aligned.m8n8.x4.trans.shared.b16 {%0,%1,%2,%3}, [%4];" \
                 : "=r"(r0), "=r"(r1), "=r"(r2), "=r"(r3) : "r"(addr))
#define MMA16816(c, a, b) \
    asm volatile("mma.sync.aligned.m16n8k16.row.col.f32.f16.f16.f32 " \
                 "{%0,%1,%2,%3}, {%4,%5,%6,%7}, {%8,%9}, {%0,%1,%2,%3};" \
                 : "+f"((c)[0]), "+f"((c)[1]), "+f"((c)[2]), "+f"((c)[3]) \
                 : "r"((a)[0]), "r"((a)[1]), "r"((a)[2]), "r"((a)[3]), \
                   "r"((b)[0]), "r"((b)[1]))
#define CP16(dst, src) \
    asm volatile("cp.async.cg.shared.global [%0], [%1], 16;" :: "r"(dst), "l"(src))
#define CP_COMMIT() asm volatile("cp.async.commit_group;" ::: "memory")
#define CP_WAIT(n)  asm volatile("cp.async.wait_group %0;" :: "n"(n) : "memory")

__device__ __forceinline__ void split2h(float f0, float f1, uint32_t& hi, uint32_t& lo) {
    __half2 h = __float22half2_rn(make_float2(f0, f1));
    float r0 = f0 - __half2float(__low2half(h));
    float r1 = f1 - __half2float(__high2half(h));
    __half2 l = __float22half2_rn(make_float2(r0, r1));
    hi = *reinterpret_cast<uint32_t*>(&h);
    lo = *reinterpret_cast<uint32_t*>(&l);
}
__device__ __forceinline__ uint32_t pack2h(float f0, float f1) {
    __half2 h = __float22half2_rn(make_float2(f0, f1));
    return *reinterpret_cast<uint32_t*>(&h);
}

// ============================================================================
// wgemm: C[m,n] = sum_k A[m,k] * B'[k,n], fp16 HMMA.
//   NPASS=1: Ahi*Bhi only;  NPASS=2: Ahi*(Bhi+Blo)
//   B_IS_KN=true : B stored [K,N] (NN);  false: [N,K] (NT)
//   EPI: 0 = fp32 out (+bias), 1 = half hi/lo out, 2 = GEMM1 special
//        (third 0 -> q hi/lo, 1 -> k fp32, 2 -> v hi/lo), 3 = half hi only.
// Block tile 128x128, K-chunk 32, 4-stage cp.async ring, 256 thr
// (8 warps 2x4, warp tile 64x32), 2 CTAs/SM.
// ============================================================================
#define NSTAGE 4
#define STG_B  24576
#define WG_SMEM (NSTAGE * STG_B)   // 96 KB
#define P_AH 0
#define P_BH 8192
#define P_BL 16384

template <bool B_IS_KN, int NPASS, int EPI, bool ADD_BIAS>
__global__ __launch_bounds__(256, 2) void wgemm(
    const hf* __restrict__ Ah,
    const hf* __restrict__ Bh, const hf* __restrict__ Bl,
    float* __restrict__ Cf, hf* __restrict__ Ch, hf* __restrict__ Cl,
    hf* __restrict__ Ch2, hf* __restrict__ Cl2,
    const float* __restrict__ bias,
    int K, long sA, long sB, long sC, int lda, int ldb, int ldc)
{
    extern __shared__ char smem[];
    const uint32_t sb = smem_u32(smem);

    const int tid  = threadIdx.x;
    const int lane = tid & 31;
    const int wid  = tid >> 5;
    const int wm   = wid >> 2;          // 0..1
    const int wn   = wid & 3;           // 0..3
    const int m0 = blockIdx.y * 128;
    const int n0 = blockIdx.x * 128;
    const long z = blockIdx.z;

    Ah += z * sA + (long)m0 * lda;
    const long boff = z * sB + (B_IS_KN ? (long)n0 : (long)n0 * ldb);
    Bh += boff;
    if (NPASS == 2) Bl += boff;
    if (EPI == 0 || EPI == 2) Cf += z * sC;
    if (EPI == 1 || EPI == 2 || EPI == 3) Ch += z * sC;
    if (EPI == 1 || EPI == 2) Cl += z * sC;
    if (EPI == 2) { Ch2 += z * sC; Cl2 += z * sC; }

    const int ln15 = lane & 15;
    const int grp  = lane >> 4;
    const int sw64 = (ln15 >> 1) & 3;

    float acc[4][4][4];
    #pragma unroll
    for (int i = 0; i < 4; i++)
        #pragma unroll
        for (int j = 0; j < 4; j++)
            #pragma unroll
            for (int q = 0; q < 4; q++) acc[i][j][q] = 0.0f;

    // -------- cp.async stage fill --------
    auto issue = [&](int chunk, int s) {
        const int k0 = chunk * 32;
        const uint32_t st = sb + s * STG_B;
        // A plane: 128 rows x 64B, swizzle c ^ ((row>>1)&3); 2 segs/thread
        #pragma unroll
        for (int i = 0; i < 2; i++) {
            const int seg = tid + i * 256;
            const int row = seg >> 2;
            const int c   = seg & 3;
            const uint32_t doff = row * 64 + (((c ^ ((row >> 1) & 3)) & 3) << 4);
            CP16(st + P_AH + doff, Ah + (long)row * lda + k0 + c * 8);
        }
        if (!B_IS_KN) {
            // B planes: 128 rows x 64B; 2 segs/thread/plane
            #pragma unroll
            for (int i = 0; i < 2; i++) {
                const int seg = tid + i * 256;
                const int row = seg >> 2;
                const int c   = seg & 3;
                const uint32_t doff = row * 64 + (((c ^ ((row >> 1) & 3)) & 3) << 4);
                const long soff = (long)row * ldb + k0 + c * 8;
                CP16(st + P_BH + doff, Bh + soff);
                if (NPASS == 2) CP16(st + P_BL + doff, Bl + soff);
            }
        } else {
            // B planes: 32 k-rows x 256B, swizzle c ^ (k&7); 2 segs/thread/plane
            #pragma unroll
            for (int i = 0; i < 2; i++) {
                const int seg = tid + i * 256;
                const int k   = seg >> 4;
                const int c   = seg & 15;
                const uint32_t doff = k * 256 + (((c ^ (k & 7)) & 15) << 4);
                const long soff = (long)(k0 + k) * ldb + c * 8;
                CP16(st + P_BH + doff, Bh + soff);
                if (NPASS == 2) CP16(st + P_BL + doff, Bl + soff);
            }
        }
    };

    // -------- fragment loads --------
    int a_row_off[4];
    #pragma unroll
    for (int i = 0; i < 4; i++)
        a_row_off[i] = (wm * 64 + i * 16 + ln15) * 64;
    int b_row_off[2];
    #pragma unroll
    for (int jp = 0; jp < 2; jp++)
        b_row_off[jp] = (wn * 32 + jp * 16 + ln15) * 64;
    const int kn_k7 = ln15 & 7;

    auto lda_frags = [&](uint32_t plane, int ks, uint32_t af[4][4]) {
        const int c = ks * 2 + grp;
        #pragma unroll
        for (int i = 0; i < 4; i++) {
            uint32_t addr = plane + a_row_off[i] + (((c ^ sw64) & 3) << 4);
            LDSM4(af[i][0], af[i][1], af[i][2], af[i][3], addr);
        }
    };
    auto ldb_frags = [&](uint32_t plane, int ks, uint32_t bf[4][2]) {
        if (B_IS_KN) {
            const uint32_t krow = (uint32_t)(ks * 16 + ln15) << 8;
            #pragma unroll
            for (int jp = 0; jp < 2; jp++) {
                const int cn = wn * 4 + jp * 2 + grp;
                uint32_t addr = plane + krow + (((cn ^ kn_k7) & 15) << 4);
                uint32_t r0, r1, r2, r3;
                LDSM4T(r0, r1, r2, r3, addr);
                bf[jp * 2    ][0] = r0; bf[jp * 2    ][1] = r1;
                bf[jp * 2 + 1][0] = r2; bf[jp * 2 + 1][1] = r3;
            }
        } else {
            const int c = ks * 2 + grp;
            #pragma unroll
            for (int jp = 0; jp < 2; jp++) {
                uint32_t addr = plane + b_row_off[jp] + (((c ^ sw64) & 3) << 4);
                uint32_t r0, r1, r2, r3;
                LDSM4(r0, r1, r2, r3, addr);
                bf[jp * 2    ][0] = r0; bf[jp * 2    ][1] = r2;
                bf[jp * 2 + 1][0] = r1; bf[jp * 2 + 1][1] = r3;
            }
        }
    };
    auto mma_pass = [&](uint32_t af[4][4], uint32_t bf[4][2]) {
        #pragma unroll
        for (int i = 0; i < 4; i++)
            #pragma unroll
            for (int j = 0; j < 4; j++)
                MMA16816(acc[i][j], af[i], bf[j]);
    };
    auto compute_chunk = [&](int s) {
        const uint32_t base = sb + s * STG_B;
        #pragma unroll
        for (int ks = 0; ks < 2; ks++) {
            uint32_t ah[4][4];
            lda_frags(base + P_AH, ks, ah);
            {
                uint32_t bh[4][2];
                ldb_frags(base + P_BH, ks, bh);
                mma_pass(ah, bh);
            }
            if (NPASS == 2) {
                uint32_t bl[4][2];
                ldb_frags(base + P_BL, ks, bl);
                mma_pass(ah, bl);
            }
        }
    };

    // -------- multistage main loop --------
    const int NC = K >> 5;
    #pragma unroll
    for (int s = 0; s < NSTAGE - 1; s++) {
        if (s < NC) { issue(s, s); }
        CP_COMMIT();
    }
    for (int c = 0; c < NC; c++) {
        CP_WAIT(NSTAGE - 2);
        __syncthreads();
        const int pf = c + NSTAGE - 1;
        if (pf < NC) { issue(pf, pf & (NSTAGE - 1)); }
        CP_COMMIT();
        compute_chunk(c & (NSTAGE - 1));
    }

    // -------- epilogue --------
    #pragma unroll
    for (int i = 0; i < 4; i++) {
        const int row = m0 + wm * 64 + i * 16 + (lane >> 2);
        #pragma unroll
        for (int j = 0; j < 4; j++) {
            const int col = n0 + wn * 32 + j * 8 + (lane & 3) * 2;
            if (EPI == 0) {
                float bv0 = 0.0f, bv1 = 0.0f;
                if (ADD_BIAS) { bv0 = bias[row]; bv1 = bias[row + 8]; }
                float2 v0 = make_float2(acc[i][j][0] + bv0, acc[i][j][1] + bv0);
                float2 v1 = make_float2(acc[i][j][2] + bv1, acc[i][j][3] + bv1);
                *reinterpret_cast<float2*>(&Cf[(long)row * ldc + col])       = v0;
                *reinterpret_cast<float2*>(&Cf[(long)(row + 8) * ldc + col]) = v1;
            } else if (EPI == 1) {
                uint32_t h0, l0, h1, l1;
                split2h(acc[i][j][0], acc[i][j][1], h0, l0);
                split2h(acc[i][j][2], acc[i][j][3], h1, l1);
                *reinterpret_cast<uint32_t*>(&Ch[(long)row * ldc + col])       = h0;
                *reinterpret_cast<uint32_t*>(&Cl[(long)row * ldc + col])       = l0;
                *reinterpret_cast<uint32_t*>(&Ch[(long)(row + 8) * ldc + col]) = h1;
                *reinterpret_cast<uint32_t*>(&Cl[(long)(row + 8) * ldc + col]) = l1;
            } else if (EPI == 3) {
                *reinterpret_cast<uint32_t*>(&Ch[(long)row * ldc + col]) =
                    pack2h(acc[i][j][0], acc[i][j][1]);
                *reinterpret_cast<uint32_t*>(&Ch[(long)(row + 8) * ldc + col]) =
                    pack2h(acc[i][j][2], acc[i][j][3]);
            } else {
                const int third = blockIdx.y >> 2;      // 4 m-tiles of 128 per 512 rows
                const int lr = row & 511;
                if (third == 1) {
                    float2 v0 = make_float2(acc[i][j][0], acc[i][j][1]);
                    float2 v1 = make_float2(acc[i][j][2], acc[i][j][3]);
                    *reinterpret_cast<float2*>(&Cf[(long)lr * ldc + col])       = v0;
                    *reinterpret_cast<float2*>(&Cf[(long)(lr + 8) * ldc + col]) = v1;
                } else {
                    hf* dh = (third == 0) ? Ch : Ch2;
                    hf* dl = (third == 0) ? Cl : Cl2;
                    uint32_t h0, l0, h1, l1;
                    split2h(acc[i][j][0], acc[i][j][1], h0, l0);
                    split2h(acc[i][j][2], acc[i][j][3], h1, l1);
                    *reinterpret_cast<uint32_t*>(&dh[(long)lr * ldc + col])       = h0;
                    *reinterpret_cast<uint32_t*>(&dl[(long)lr * ldc + col])       = l0;
                    *reinterpret_cast<uint32_t*>(&dh[(long)(lr + 8) * ldc + col]) = h1;
                    *reinterpret_cast<uint32_t*>(&dl[(long)(lr + 8) * ldc + col]) = l1;
                }
            }
        }
    }
}

// ============================================================================
// split kernels: fp32 -> half hi(/lo)
// ============================================================================
__global__ __launch_bounds__(256) void split_arr(
    const float* __restrict__ s, hf* __restrict__ h, hf* __restrict__ l, long n)
{
    long i = ((long)blockIdx.x * 256 + threadIdx.x) * 4;
    if (i >= n) return;
    float4 v = *reinterpret_cast<const float4*>(s + i);
    uint32_t h0, l0, h1, l1;
    split2h(v.x, v.y, h0, l0);
    split2h(v.z, v.w, h1, l1);
    *reinterpret_cast<uint2*>(h + i) = make_uint2(h0, h1);
    *reinterpret_cast<uint2*>(l + i) = make_uint2(l0, l1);
}
__global__ __launch_bounds__(256) void split_hi(
    const float* __restrict__ s, hf* __restrict__ h, long n)
{
    long i = ((long)blockIdx.x * 256 + threadIdx.x) * 4;
    if (i >= n) return;
    float4 v = *reinterpret_cast<const float4*>(s + i);
    *reinterpret_cast<uint2*>(h + i) = make_uint2(pack2h(v.x, v.y), pack2h(v.z, v.w));
}

// ============================================================================
// softmax over L on kf fp32 -> half hi only
// ============================================================================
__global__ __launch_bounds__(256) void softmax_h(
    const float* __restrict__ kf, hf* __restrict__ kh)
{
    const int r = blockIdx.x;
    const int b = blockIdx.y;
    const long off = ((long)b * CC + r) * LL;
    const float* p = kf + off;
    const int tid = threadIdx.x;
    __shared__ float red[8];

    float v[16];
    float mx = -1e30f;
    #pragma unroll
    for (int i = 0; i < 16; i++) { v[i] = p[tid + i * 256]; mx = fmaxf(mx, v[i]); }
    #pragma unroll
    for (int o = 16; o > 0; o >>= 1) mx = fmaxf(mx, __shfl_xor_sync(0xffffffffu, mx, o));
    if ((tid & 31) == 0) red[tid >> 5] = mx;
    __syncthreads();
    if (tid < 32) {
        float m2 = (tid < 8) ? red[tid] : -1e30f;
        #pragma unroll
        for (int o = 4; o > 0; o >>= 1) m2 = fmaxf(m2, __shfl_xor_sync(0xffffffffu, m2, o));
        if (tid == 0) red[0] = m2;
    }
    __syncthreads();
    mx = red[0];
    __syncthreads();

    float s = 0.0f;
    #pragma unroll
    for (int i = 0; i < 16; i++) { v[i] = __expf(v[i] - mx); s += v[i]; }
    #pragma unroll
    for (int o = 16; o > 0; o >>= 1) s += __shfl_xor_sync(0xffffffffu, s, o);
    if ((tid & 31) == 0) red[tid >> 5] = s;
    __syncthreads();
    if (tid < 32) {
        float s2 = (tid < 8) ? red[tid] : 0.0f;
        #pragma unroll
        for (int o = 4; o > 0; o >>= 1) s2 += __shfl_xor_sync(0xffffffffu, s2, o);
        if (tid == 0) red[0] = s2;
    }
    __syncthreads();
    const float inv = 1.0f / red[0];

    #pragma unroll
    for (int i = 0; i < 16; i++)
        kh[off + tid + i * 256] = __float2half_rn(v[i] * inv);
}

// ============================================================================
extern "C" void kernel_launch(void* const* d_in, const int* in_sizes, int n_in,
                              void* d_out, int out_size)
{
    const float* x = nullptr; const float* w_qkv = nullptr;
    const float* w_out = nullptr; const float* b_out = nullptr;
    for (int i = 0; i < n_in; i++) {
        switch (in_sizes[i]) {
            case 33554432: x     = (const float*)d_in[i]; break;
            case 786432:   w_qkv = (const float*)d_in[i]; break;
            case 262144:   w_out = (const float*)d_in[i]; break;
            case 512:      b_out = (const float*)d_in[i]; break;
            default: break;
        }
    }
    float* y = (float*)d_out;

    float* kf;  cudaGetSymbolAddress((void**)&kf,  g_kf);
    hf *xh, *qh, *ql, *vh, *vl, *kh, *ch, *cl, *mh, *wqh, *woh;
    cudaGetSymbolAddress((void**)&xh, g_xh);
    cudaGetSymbolAddress((void**)&qh, g_qh);   cudaGetSymbolAddress((void**)&ql, g_ql);
    cudaGetSymbolAddress((void**)&vh, g_vh);   cudaGetSymbolAddress((void**)&vl, g_vl);
    cudaGetSymbolAddress((void**)&kh, g_kh);
    cudaGetSymbolAddress((void**)&ch, g_ch);   cudaGetSymbolAddress((void**)&cl, g_cl);
    cudaGetSymbolAddress((void**)&mh, g_mh);
    cudaGetSymbolAddress((void**)&wqh, g_wqh);
    cudaGetSymbolAddress((void**)&woh, g_woh);

    cudaFuncSetAttribute(wgemm<true,  1, 2, false>, cudaFuncAttributeMaxDynamicSharedMemorySize, WG_SMEM);
    cudaFuncSetAttribute(wgemm<false, 2, 1, false>, cudaFuncAttributeMaxDynamicSharedMemorySize, WG_SMEM);
    cudaFuncSetAttribute(wgemm<false, 2, 3, false>, cudaFuncAttributeMaxDynamicSharedMemorySize, WG_SMEM);
    cudaFuncSetAttribute(wgemm<true,  2, 0, true >, cudaFuncAttributeMaxDynamicSharedMemorySize, WG_SMEM);

    const long sBig = (long)CC * LL;
    const long sCtx = (long)CC * CC;

    // 0) pre-split inputs: everything hi only except v/q/ctx intermediates
    split_hi<<<(unsigned)((size_t)BB * CC * LL / 1024), 256>>>(x, xh, (long)BB * CC * LL);
    split_hi<<<3 * CC * CC / 1024, 256>>>(w_qkv, wqh, 3 * CC * CC);
    split_hi<<<CC * CC / 1024, 256>>>(w_out, woh, CC * CC);

    // 1) qkv = w_qkv @ x (NN, 1-pass): q -> hi/lo, k -> fp32, v -> hi/lo
    wgemm<true, 1, 2, false><<<dim3(LL / 128, (3 * CC) / 128, BB), 256, WG_SMEM>>>(
        wqh, xh, nullptr, kf, qh, ql, vh, vl, nullptr,
        CC, 0, sBig, sBig, CC, LL, LL);

    // 2) softmax over L on k -> hi
    softmax_h<<<dim3(CC, BB), 256>>>(kf, kh);

    // 3) ctx = k_sm @ v^T (NT, 2-pass) -> hi/lo
    wgemm<false, 2, 1, false><<<dim3(CC / 128, CC / 128, BB), 256, WG_SMEM>>>(
        kh, vh, vl, nullptr, ch, cl, nullptr, nullptr, nullptr,
        LL, sBig, sBig, sCtx, LL, LL, CC);

    // 4) M = w_out @ ctx^T (NT, 2-pass) -> hi only
    wgemm<false, 2, 3, false><<<dim3(CC / 128, CC / 128, BB), 256, WG_SMEM>>>(
        woh, ch, cl, nullptr, mh, nullptr, nullptr, nullptr, nullptr,
        CC, 0, sCtx, sCtx, CC, CC, CC);

    // 5) y = M @ q + b_out (NN, 2-pass, fp32 + bias)
    wgemm<true, 2, 0, true><<<dim3(LL / 128, CC / 128, BB), 256, WG_SMEM>>>(
        mh, qh, ql, y, nullptr, nullptr, nullptr, nullptr, b_out,
        CC, sCtx, sBig, sBig, CC, LL, LL);

    (void)out_size;
}

// round 12
// speedup vs baseline: 1.3419x; 1.3390x over previous
#include <cuda_runtime.h>
#include <cuda_fp16.h>
#include <cstdint>

// Problem shape (fixed)
#define BB 16
#define CC 512
#define LL 4096

typedef __half hf;

// ---------------- Scratch (device globals; no allocation allowed) -----------
__device__ __align__(256) float g_kf[(size_t)BB * CC * LL];   // k pre-softmax fp32
__device__ __align__(256) hf g_xh[(size_t)BB * CC * LL];
__device__ __align__(256) hf g_qh[(size_t)BB * CC * LL];
__device__ __align__(256) hf g_vh[(size_t)BB * CC * LL];
__device__ __align__(256) hf g_kh[(size_t)BB * CC * LL];
__device__ __align__(256) hf g_ch[(size_t)BB * CC * CC];
__device__ __align__(256) hf g_mh[(size_t)BB * CC * CC];
__device__ __align__(256) hf g_wqh[3 * CC * CC];
__device__ __align__(256) hf g_woh[CC * CC];

// ---------------- PTX helpers ----------------
__device__ __forceinline__ uint32_t smem_u32(const void* p) {
    uint32_t a;
    asm("{ .reg .u64 t; cvta.to.shared.u64 t, %1; cvt.u32.u64 %0, t; }" : "=r"(a) : "l"(p));
    return a;
}
#define LDSM4(r0, r1, r2, r3, addr) \
    asm volatile("ldmatrix.sync.aligned.m8n8.x4.shared.b16 {%0,%1,%2,%3}, [%4];" \
                 : "=r"(r0), "=r"(r1), "=r"(r2), "=r"(r3) : "r"(addr))
#define LDSM4T(r0, r1, r2, r3, addr) \
    asm volatile("ldmatrix.sync.aligned.m8n8.x4.trans.shared.b16 {%0,%1,%2,%3}, [%4];" \
                 : "=r"(r0), "=r"(r1), "=r"(r2), "=r"(r3) : "r"(addr))
#define MMA16816(c, a, b) \
    asm volatile("mma.sync.aligned.m16n8k16.row.col.f32.f16.f16.f32 " \
                 "{%0,%1,%2,%3}, {%4,%5,%6,%7}, {%8,%9}, {%0,%1,%2,%3};" \
                 : "+f"((c)[0]), "+f"((c)[1]), "+f"((c)[2]), "+f"((c)[3]) \
                 : "r"((a)[0]), "r"((a)[1]), "r"((a)[2]), "r"((a)[3]), \
                   "r"((b)[0]), "r"((b)[1]))
#define CP16(dst, src) \
    asm volatile("cp.async.cg.shared.global [%0], [%1], 16;" :: "r"(dst), "l"(src))
#define CP_COMMIT() asm volatile("cp.async.commit_group;" ::: "memory")
#define CP_WAIT(n)  asm volatile("cp.async.wait_group %0;" :: "n"(n) : "memory")

__device__ __forceinline__ uint32_t pack2h(float f0, float f1) {
    __half2 h = __float22half2_rn(make_float2(f0, f1));
    return *reinterpret_cast<uint32_t*>(&h);
}

// ============================================================================
// wgemm: C[m,n] = sum_k A[m,k] * B'[k,n], fp16 1-pass HMMA (hi planes only).
//   B_IS_KN=true : B stored [K,N] (NN);  false: [N,K] (NT)
//   EPI: 0 = fp32 out (+bias), 2 = GEMM1 special (third 0 -> q hi,
//        1 -> k fp32, 2 -> v hi), 3 = half hi out.
// Block tile 128x128, K-chunk 32, 4-stage cp.async ring (16KB stages),
// 256 thr (8 warps 2x4, warp tile 64x32), 2 CTAs/SM.
// ============================================================================
#define NSTAGE 4
#define STG_B  16384
#define WG_SMEM (NSTAGE * STG_B)   // 64 KB
#define P_AH 0
#define P_BH 8192

template <bool B_IS_KN, int EPI, bool ADD_BIAS>
__global__ __launch_bounds__(256, 2) void wgemm(
    const hf* __restrict__ Ah, const hf* __restrict__ Bh,
    float* __restrict__ Cf, hf* __restrict__ Ch, hf* __restrict__ Ch2,
    const float* __restrict__ bias,
    int K, long sA, long sB, long sC, int lda, int ldb, int ldc)
{
    extern __shared__ char smem[];
    const uint32_t sb = smem_u32(smem);

    const int tid  = threadIdx.x;
    const int lane = tid & 31;
    const int wid  = tid >> 5;
    const int wm   = wid >> 2;          // 0..1
    const int wn   = wid & 3;           // 0..3
    const int m0 = blockIdx.y * 128;
    const int n0 = blockIdx.x * 128;
    const long z = blockIdx.z;

    Ah += z * sA + (long)m0 * lda;
    Bh += z * sB + (B_IS_KN ? (long)n0 : (long)n0 * ldb);
    if (EPI == 0 || EPI == 2) Cf += z * sC;
    if (EPI == 2 || EPI == 3) Ch += z * sC;
    if (EPI == 2) Ch2 += z * sC;

    const int ln15 = lane & 15;
    const int grp  = lane >> 4;
    const int sw64 = (ln15 >> 1) & 3;

    float acc[4][4][4];
    #pragma unroll
    for (int i = 0; i < 4; i++)
        #pragma unroll
        for (int j = 0; j < 4; j++)
            #pragma unroll
            for (int q = 0; q < 4; q++) acc[i][j][q] = 0.0f;

    // -------- cp.async stage fill --------
    auto issue = [&](int chunk, int s) {
        const int k0 = chunk * 32;
        const uint32_t st = sb + s * STG_B;
        // A plane: 128 rows x 64B, swizzle c ^ ((row>>1)&3); 2 segs/thread
        #pragma unroll
        for (int i = 0; i < 2; i++) {
            const int seg = tid + i * 256;
            const int row = seg >> 2;
            const int c   = seg & 3;
            const uint32_t doff = row * 64 + (((c ^ ((row >> 1) & 3)) & 3) << 4);
            CP16(st + P_AH + doff, Ah + (long)row * lda + k0 + c * 8);
        }
        if (!B_IS_KN) {
            // B plane: 128 rows x 64B; 2 segs/thread
            #pragma unroll
            for (int i = 0; i < 2; i++) {
                const int seg = tid + i * 256;
                const int row = seg >> 2;
                const int c   = seg & 3;
                const uint32_t doff = row * 64 + (((c ^ ((row >> 1) & 3)) & 3) << 4);
                CP16(st + P_BH + doff, Bh + (long)row * ldb + k0 + c * 8);
            }
        } else {
            // B plane: 32 k-rows x 256B, swizzle c ^ (k&7); 2 segs/thread
            #pragma unroll
            for (int i = 0; i < 2; i++) {
                const int seg = tid + i * 256;
                const int k   = seg >> 4;
                const int c   = seg & 15;
                const uint32_t doff = k * 256 + (((c ^ (k & 7)) & 15) << 4);
                CP16(st + P_BH + doff, Bh + (long)(k0 + k) * ldb + c * 8);
            }
        }
    };

    // -------- fragment loads --------
    int a_row_off[4];
    #pragma unroll
    for (int i = 0; i < 4; i++)
        a_row_off[i] = (wm * 64 + i * 16 + ln15) * 64;
    int b_row_off[2];
    #pragma unroll
    for (int jp = 0; jp < 2; jp++)
        b_row_off[jp] = (wn * 32 + jp * 16 + ln15) * 64;
    const int kn_k7 = ln15 & 7;

    auto lda_frags = [&](uint32_t plane, int ks, uint32_t af[4][4]) {
        const int c = ks * 2 + grp;
        #pragma unroll
        for (int i = 0; i < 4; i++) {
            uint32_t addr = plane + a_row_off[i] + (((c ^ sw64) & 3) << 4);
            LDSM4(af[i][0], af[i][1], af[i][2], af[i][3], addr);
        }
    };
    auto ldb_frags = [&](uint32_t plane, int ks, uint32_t bf[4][2]) {
        if (B_IS_KN) {
            const uint32_t krow = (uint32_t)(ks * 16 + ln15) << 8;
            #pragma unroll
            for (int jp = 0; jp < 2; jp++) {
                const int cn = wn * 4 + jp * 2 + grp;
                uint32_t addr = plane + krow + (((cn ^ kn_k7) & 15) << 4);
                uint32_t r0, r1, r2, r3;
                LDSM4T(r0, r1, r2, r3, addr);
                bf[jp * 2    ][0] = r0; bf[jp * 2    ][1] = r1;
                bf[jp * 2 + 1][0] = r2; bf[jp * 2 + 1][1] = r3;
            }
        } else {
            const int c = ks * 2 + grp;
            #pragma unroll
            for (int jp = 0; jp < 2; jp++) {
                uint32_t addr = plane + b_row_off[jp] + (((c ^ sw64) & 3) << 4);
                uint32_t r0, r1, r2, r3;
                LDSM4(r0, r1, r2, r3, addr);
                bf[jp * 2    ][0] = r0; bf[jp * 2    ][1] = r2;
                bf[jp * 2 + 1][0] = r1; bf[jp * 2 + 1][1] = r3;
            }
        }
    };
    auto compute_chunk = [&](int s) {
        const uint32_t base = sb + s * STG_B;
        #pragma unroll
        for (int ks = 0; ks < 2; ks++) {
            uint32_t ah[4][4], bh[4][2];
            lda_frags(base + P_AH, ks, ah);
            ldb_frags(base + P_BH, ks, bh);
            #pragma unroll
            for (int i = 0; i < 4; i++)
                #pragma unroll
                for (int j = 0; j < 4; j++)
                    MMA16816(acc[i][j], ah[i], bh[j]);
        }
    };

    // -------- multistage main loop --------
    const int NC = K >> 5;
    #pragma unroll
    for (int s = 0; s < NSTAGE - 1; s++) {
        if (s < NC) { issue(s, s); }
        CP_COMMIT();
    }
    for (int c = 0; c < NC; c++) {
        CP_WAIT(NSTAGE - 2);
        __syncthreads();
        const int pf = c + NSTAGE - 1;
        if (pf < NC) { issue(pf, pf & (NSTAGE - 1)); }
        CP_COMMIT();
        compute_chunk(c & (NSTAGE - 1));
    }

    // -------- epilogue --------
    #pragma unroll
    for (int i = 0; i < 4; i++) {
        const int row = m0 + wm * 64 + i * 16 + (lane >> 2);
        #pragma unroll
        for (int j = 0; j < 4; j++) {
            const int col = n0 + wn * 32 + j * 8 + (lane & 3) * 2;
            if (EPI == 0) {
                float bv0 = 0.0f, bv1 = 0.0f;
                if (ADD_BIAS) { bv0 = bias[row]; bv1 = bias[row + 8]; }
                float2 v0 = make_float2(acc[i][j][0] + bv0, acc[i][j][1] + bv0);
                float2 v1 = make_float2(acc[i][j][2] + bv1, acc[i][j][3] + bv1);
                *reinterpret_cast<float2*>(&Cf[(long)row * ldc + col])       = v0;
                *reinterpret_cast<float2*>(&Cf[(long)(row + 8) * ldc + col]) = v1;
            } else if (EPI == 3) {
                *reinterpret_cast<uint32_t*>(&Ch[(long)row * ldc + col]) =
                    pack2h(acc[i][j][0], acc[i][j][1]);
                *reinterpret_cast<uint32_t*>(&Ch[(long)(row + 8) * ldc + col]) =
                    pack2h(acc[i][j][2], acc[i][j][3]);
            } else {
                const int third = blockIdx.y >> 2;      // 4 m-tiles of 128 per 512 rows
                const int lr = row & 511;
                if (third == 1) {
                    float2 v0 = make_float2(acc[i][j][0], acc[i][j][1]);
                    float2 v1 = make_float2(acc[i][j][2], acc[i][j][3]);
                    *reinterpret_cast<float2*>(&Cf[(long)lr * ldc + col])       = v0;
                    *reinterpret_cast<float2*>(&Cf[(long)(lr + 8) * ldc + col]) = v1;
                } else {
                    hf* dh = (third == 0) ? Ch : Ch2;
                    *reinterpret_cast<uint32_t*>(&dh[(long)lr * ldc + col]) =
                        pack2h(acc[i][j][0], acc[i][j][1]);
                    *reinterpret_cast<uint32_t*>(&dh[(long)(lr + 8) * ldc + col]) =
                        pack2h(acc[i][j][2], acc[i][j][3]);
                }
            }
        }
    }
}

// ============================================================================
// split kernel: fp32 -> half hi
// ============================================================================
__global__ __launch_bounds__(256) void split_hi(
    const float* __restrict__ s, hf* __restrict__ h, long n)
{
    long i = ((long)blockIdx.x * 256 + threadIdx.x) * 4;
    if (i >= n) return;
    float4 v = *reinterpret_cast<const float4*>(s + i);
    *reinterpret_cast<uint2*>(h + i) = make_uint2(pack2h(v.x, v.y), pack2h(v.z, v.w));
}

// ============================================================================
// softmax over L on kf fp32 -> half hi
// ============================================================================
__global__ __launch_bounds__(256) void softmax_h(
    const float* __restrict__ kf, hf* __restrict__ kh)
{
    const int r = blockIdx.x;
    const int b = blockIdx.y;
    const long off = ((long)b * CC + r) * LL;
    const float* p = kf + off;
    const int tid = threadIdx.x;
    __shared__ float red[8];

    float v[16];
    float mx = -1e30f;
    #pragma unroll
    for (int i = 0; i < 16; i++) { v[i] = p[tid + i * 256]; mx = fmaxf(mx, v[i]); }
    #pragma unroll
    for (int o = 16; o > 0; o >>= 1) mx = fmaxf(mx, __shfl_xor_sync(0xffffffffu, mx, o));
    if ((tid & 31) == 0) red[tid >> 5] = mx;
    __syncthreads();
    if (tid < 32) {
        float m2 = (tid < 8) ? red[tid] : -1e30f;
        #pragma unroll
        for (int o = 4; o > 0; o >>= 1) m2 = fmaxf(m2, __shfl_xor_sync(0xffffffffu, m2, o));
        if (tid == 0) red[0] = m2;
    }
    __syncthreads();
    mx = red[0];
    __syncthreads();

    float s = 0.0f;
    #pragma unroll
    for (int i = 0; i < 16; i++) { v[i] = __expf(v[i] - mx); s += v[i]; }
    #pragma unroll
    for (int o = 16; o > 0; o >>= 1) s += __shfl_xor_sync(0xffffffffu, s, o);
    if ((tid & 31) == 0) red[tid >> 5] = s;
    __syncthreads();
    if (tid < 32) {
        float s2 = (tid < 8) ? red[tid] : 0.0f;
        #pragma unroll
        for (int o = 4; o > 0; o >>= 1) s2 += __shfl_xor_sync(0xffffffffu, s2, o);
        if (tid == 0) red[0] = s2;
    }
    __syncthreads();
    const float inv = 1.0f / red[0];

    #pragma unroll
    for (int i = 0; i < 16; i++)
        kh[off + tid + i * 256] = __float2half_rn(v[i] * inv);
}

// ============================================================================
extern "C" void kernel_launch(void* const* d_in, const int* in_sizes, int n_in,
                              void* d_out, int out_size)
{
    const float* x = nullptr; const float* w_qkv = nullptr;
    const float* w_out = nullptr; const float* b_out = nullptr;
    for (int i = 0; i < n_in; i++) {
        switch (in_sizes[i]) {
            case 33554432: x     = (const float*)d_in[i]; break;
            case 786432:   w_qkv = (const float*)d_in[i]; break;
            case 262144:   w_out = (const float*)d_in[i]; break;
            case 512:      b_out = (const float*)d_in[i]; break;
            default: break;
        }
    }
    float* y = (float*)d_out;

    float* kf;  cudaGetSymbolAddress((void**)&kf,  g_kf);
    hf *xh, *qh, *vh, *kh, *ch, *mh, *wqh, *woh;
    cudaGetSymbolAddress((void**)&xh, g_xh);
    cudaGetSymbolAddress((void**)&qh, g_qh);
    cudaGetSymbolAddress((void**)&vh, g_vh);
    cudaGetSymbolAddress((void**)&kh, g_kh);
    cudaGetSymbolAddress((void**)&ch, g_ch);
    cudaGetSymbolAddress((void**)&mh, g_mh);
    cudaGetSymbolAddress((void**)&wqh, g_wqh);
    cudaGetSymbolAddress((void**)&woh, g_woh);

    cudaFuncSetAttribute(wgemm<true,  2, false>, cudaFuncAttributeMaxDynamicSharedMemorySize, WG_SMEM);
    cudaFuncSetAttribute(wgemm<false, 3, false>, cudaFuncAttributeMaxDynamicSharedMemorySize, WG_SMEM);
    cudaFuncSetAttribute(wgemm<true,  0, true >, cudaFuncAttributeMaxDynamicSharedMemorySize, WG_SMEM);

    const long sBig = (long)CC * LL;
    const long sCtx = (long)CC * CC;

    // 0) pre-split inputs to fp16 hi
    split_hi<<<(unsigned)((size_t)BB * CC * LL / 1024), 256>>>(x, xh, (long)BB * CC * LL);
    split_hi<<<3 * CC * CC / 1024, 256>>>(w_qkv, wqh, 3 * CC * CC);
    split_hi<<<CC * CC / 1024, 256>>>(w_out, woh, CC * CC);

    // 1) qkv = w_qkv @ x (NN): q -> hi, k -> fp32, v -> hi
    wgemm<true, 2, false><<<dim3(LL / 128, (3 * CC) / 128, BB), 256, WG_SMEM>>>(
        wqh, xh, kf, qh, vh, nullptr,
        CC, 0, sBig, sBig, CC, LL, LL);

    // 2) softmax over L on k -> hi
    softmax_h<<<dim3(CC, BB), 256>>>(kf, kh);

    // 3) ctx = k_sm @ v^T (NT) -> hi
    wgemm<false, 3, false><<<dim3(CC / 128, CC / 128, BB), 256, WG_SMEM>>>(
        kh, vh, nullptr, ch, nullptr, nullptr,
        LL, sBig, sBig, sCtx, LL, LL, CC);

    // 4) M = w_out @ ctx^T (NT) -> hi
    wgemm<false, 3, false><<<dim3(CC / 128, CC / 128, BB), 256, WG_SMEM>>>(
        woh, ch, nullptr, mh, nullptr, nullptr,
        CC, 0, sCtx, sCtx, CC, CC, CC);

    // 5) y = M @ q + b_out (NN, fp32 + bias)
    wgemm<true, 0, true><<<dim3(LL / 128, CC / 128, BB), 256, WG_SMEM>>>(
        mh, qh, y, nullptr, nullptr, b_out,
        CC, sCtx, sBig, sBig, CC, LL, LL);

    (void)out_size;
}

// round 13
// speedup vs baseline: 1.4143x; 1.0539x over previous
#include <cuda_runtime.h>
#include <cuda_fp16.h>
#include <cstdint>

// Problem shape (fixed)
#define BB 16
#define CC 512
#define LL 4096

typedef __half hf;

// ---------------- Scratch (device globals; no allocation allowed) -----------
__device__ __align__(256) hf g_xh[(size_t)BB * CC * LL];
__device__ __align__(256) hf g_qh[(size_t)BB * CC * LL];
__device__ __align__(256) hf g_vh[(size_t)BB * CC * LL];
__device__ __align__(256) hf g_kh[(size_t)BB * CC * LL];   // logits, then softmax in-place
__device__ __align__(256) hf g_ch[(size_t)BB * CC * CC];
__device__ __align__(256) hf g_mh[(size_t)BB * CC * CC];
__device__ __align__(256) hf g_wqh[3 * CC * CC];
__device__ __align__(256) hf g_woh[CC * CC];

// ---------------- PTX helpers ----------------
__device__ __forceinline__ uint32_t smem_u32(const void* p) {
    uint32_t a;
    asm("{ .reg .u64 t; cvta.to.shared.u64 t, %1; cvt.u32.u64 %0, t; }" : "=r"(a) : "l"(p));
    return a;
}
#define LDSM4(r0, r1, r2, r3, addr) \
    asm volatile("ldmatrix.sync.aligned.m8n8.x4.shared.b16 {%0,%1,%2,%3}, [%4];" \
                 : "=r"(r0), "=r"(r1), "=r"(r2), "=r"(r3) : "r"(addr))
#define LDSM4T(r0, r1, r2, r3, addr) \
    asm volatile("ldmatrix.sync.aligned.m8n8.x4.trans.shared.b16 {%0,%1,%2,%3}, [%4];" \
                 : "=r"(r0), "=r"(r1), "=r"(r2), "=r"(r3) : "r"(addr))
#define MMA16816(c, a, b) \
    asm volatile("mma.sync.aligned.m16n8k16.row.col.f32.f16.f16.f32 " \
                 "{%0,%1,%2,%3}, {%4,%5,%6,%7}, {%8,%9}, {%0,%1,%2,%3};" \
                 : "+f"((c)[0]), "+f"((c)[1]), "+f"((c)[2]), "+f"((c)[3]) \
                 : "r"((a)[0]), "r"((a)[1]), "r"((a)[2]), "r"((a)[3]), \
                   "r"((b)[0]), "r"((b)[1]))
#define CP16(dst, src) \
    asm volatile("cp.async.cg.shared.global [%0], [%1], 16;" :: "r"(dst), "l"(src))
#define CP_COMMIT() asm volatile("cp.async.commit_group;" ::: "memory")
#define CP_WAIT(n)  asm volatile("cp.async.wait_group %0;" :: "n"(n) : "memory")

__device__ __forceinline__ uint32_t pack2h(float f0, float f1) {
    __half2 h = __float22half2_rn(make_float2(f0, f1));
    return *reinterpret_cast<uint32_t*>(&h);
}

// ============================================================================
// wgemm: C[m,n] = sum_k A[m,k] * B'[k,n], fp16 1-pass HMMA.
//   B_IS_KN=true : B stored [K,N] (NN);  false: [N,K] (NT)
//   EPI: 0 = fp32 out (+bias), 2 = GEMM1 3-way fp16 (third 0->C0 q,
//        1->C1 k-logits, 2->C2 v), 3 = fp16 out (C0).
// Block tile 128x128, K-chunk 32, 4-stage cp.async ring (16KB stages),
// 128 thr (4 warps 2x2, warp tile 64x64), 2 CTAs/SM.
// ============================================================================
#define NSTAGE 4
#define STG_B  16384
#define WG_SMEM (NSTAGE * STG_B)   // 64 KB
#define P_AH 0
#define P_BH 8192

template <bool B_IS_KN, int EPI, bool ADD_BIAS>
__global__ __launch_bounds__(128, 2) void wgemm(
    const hf* __restrict__ Ah, const hf* __restrict__ Bh,
    float* __restrict__ Cf, hf* __restrict__ C0, hf* __restrict__ C1,
    hf* __restrict__ C2, const float* __restrict__ bias,
    int K, long sA, long sB, long sC, int lda, int ldb, int ldc)
{
    extern __shared__ char smem[];
    const uint32_t sb = smem_u32(smem);

    const int tid  = threadIdx.x;
    const int lane = tid & 31;
    const int wid  = tid >> 5;          // 0..3
    const int wm   = wid >> 1;          // 0..1
    const int wn   = wid & 1;           // 0..1
    const int m0 = blockIdx.y * 128;
    const int n0 = blockIdx.x * 128;
    const long z = blockIdx.z;

    Ah += z * sA + (long)m0 * lda;
    Bh += z * sB + (B_IS_KN ? (long)n0 : (long)n0 * ldb);
    if (EPI == 0) Cf += z * sC;
    if (EPI == 2) { C0 += z * sC; C1 += z * sC; C2 += z * sC; }
    if (EPI == 3) C0 += z * sC;

    const int ln15 = lane & 15;
    const int grp  = lane >> 4;
    const int sw64 = (ln15 >> 1) & 3;

    float acc[4][8][4];
    #pragma unroll
    for (int i = 0; i < 4; i++)
        #pragma unroll
        for (int j = 0; j < 8; j++)
            #pragma unroll
            for (int q = 0; q < 4; q++) acc[i][j][q] = 0.0f;

    // -------- cp.async stage fill (128 threads: 4 segs/plane/thread) --------
    auto issue = [&](int chunk, int s) {
        const int k0 = chunk * 32;
        const uint32_t st = sb + s * STG_B;
        // A plane: 128 rows x 64B, swizzle c ^ ((row>>1)&3)
        #pragma unroll
        for (int i = 0; i < 4; i++) {
            const int seg = tid + i * 128;
            const int row = seg >> 2;
            const int c   = seg & 3;
            const uint32_t doff = row * 64 + (((c ^ ((row >> 1) & 3)) & 3) << 4);
            CP16(st + P_AH + doff, Ah + (long)row * lda + k0 + c * 8);
        }
        if (!B_IS_KN) {
            #pragma unroll
            for (int i = 0; i < 4; i++) {
                const int seg = tid + i * 128;
                const int row = seg >> 2;
                const int c   = seg & 3;
                const uint32_t doff = row * 64 + (((c ^ ((row >> 1) & 3)) & 3) << 4);
                CP16(st + P_BH + doff, Bh + (long)row * ldb + k0 + c * 8);
            }
        } else {
            // B plane: 32 k-rows x 256B, swizzle c ^ (k&7)
            #pragma unroll
            for (int i = 0; i < 4; i++) {
                const int seg = tid + i * 128;
                const int k   = seg >> 4;
                const int c   = seg & 15;
                const uint32_t doff = k * 256 + (((c ^ (k & 7)) & 15) << 4);
                CP16(st + P_BH + doff, Bh + (long)(k0 + k) * ldb + c * 8);
            }
        }
    };

    // -------- fragment loads --------
    int a_row_off[4];
    #pragma unroll
    for (int i = 0; i < 4; i++)
        a_row_off[i] = (wm * 64 + i * 16 + ln15) * 64;
    int b_row_off[4];
    #pragma unroll
    for (int jp = 0; jp < 4; jp++)
        b_row_off[jp] = (wn * 64 + jp * 16 + ln15) * 64;
    const int kn_k7 = ln15 & 7;

    auto lda_frags = [&](uint32_t plane, int ks, uint32_t af[4][4]) {
        const int c = ks * 2 + grp;
        #pragma unroll
        for (int i = 0; i < 4; i++) {
            uint32_t addr = plane + a_row_off[i] + (((c ^ sw64) & 3) << 4);
            LDSM4(af[i][0], af[i][1], af[i][2], af[i][3], addr);
        }
    };
    auto ldb_frags = [&](uint32_t plane, int ks, uint32_t bf[8][2]) {
        if (B_IS_KN) {
            const uint32_t krow = (uint32_t)(ks * 16 + ln15) << 8;
            #pragma unroll
            for (int jp = 0; jp < 4; jp++) {
                const int cn = wn * 8 + jp * 2 + grp;
                uint32_t addr = plane + krow + (((cn ^ kn_k7) & 15) << 4);
                uint32_t r0, r1, r2, r3;
                LDSM4T(r0, r1, r2, r3, addr);
                bf[jp * 2    ][0] = r0; bf[jp * 2    ][1] = r1;
                bf[jp * 2 + 1][0] = r2; bf[jp * 2 + 1][1] = r3;
            }
        } else {
            const int c = ks * 2 + grp;
            #pragma unroll
            for (int jp = 0; jp < 4; jp++) {
                uint32_t addr = plane + b_row_off[jp] + (((c ^ sw64) & 3) << 4);
                uint32_t r0, r1, r2, r3;
                LDSM4(r0, r1, r2, r3, addr);
                bf[jp * 2    ][0] = r0; bf[jp * 2    ][1] = r2;
                bf[jp * 2 + 1][0] = r1; bf[jp * 2 + 1][1] = r3;
            }
        }
    };
    auto compute_chunk = [&](int s) {
        const uint32_t base = sb + s * STG_B;
        #pragma unroll
        for (int ks = 0; ks < 2; ks++) {
            uint32_t ah[4][4], bh[8][2];
            lda_frags(base + P_AH, ks, ah);
            ldb_frags(base + P_BH, ks, bh);
            #pragma unroll
            for (int i = 0; i < 4; i++)
                #pragma unroll
                for (int j = 0; j < 8; j++)
                    MMA16816(acc[i][j], ah[i], bh[j]);
        }
    };

    // -------- multistage main loop --------
    const int NC = K >> 5;
    #pragma unroll
    for (int s = 0; s < NSTAGE - 1; s++) {
        if (s < NC) { issue(s, s); }
        CP_COMMIT();
    }
    for (int c = 0; c < NC; c++) {
        CP_WAIT(NSTAGE - 2);
        __syncthreads();
        const int pf = c + NSTAGE - 1;
        if (pf < NC) { issue(pf, pf & (NSTAGE - 1)); }
        CP_COMMIT();
        compute_chunk(c & (NSTAGE - 1));
    }

    // -------- epilogue --------
    #pragma unroll
    for (int i = 0; i < 4; i++) {
        const int row = m0 + wm * 64 + i * 16 + (lane >> 2);
        #pragma unroll
        for (int j = 0; j < 8; j++) {
            const int col = n0 + wn * 64 + j * 8 + (lane & 3) * 2;
            if (EPI == 0) {
                float bv0 = 0.0f, bv1 = 0.0f;
                if (ADD_BIAS) { bv0 = bias[row]; bv1 = bias[row + 8]; }
                float2 v0 = make_float2(acc[i][j][0] + bv0, acc[i][j][1] + bv0);
                float2 v1 = make_float2(acc[i][j][2] + bv1, acc[i][j][3] + bv1);
                *reinterpret_cast<float2*>(&Cf[(long)row * ldc + col])       = v0;
                *reinterpret_cast<float2*>(&Cf[(long)(row + 8) * ldc + col]) = v1;
            } else if (EPI == 3) {
                *reinterpret_cast<uint32_t*>(&C0[(long)row * ldc + col]) =
                    pack2h(acc[i][j][0], acc[i][j][1]);
                *reinterpret_cast<uint32_t*>(&C0[(long)(row + 8) * ldc + col]) =
                    pack2h(acc[i][j][2], acc[i][j][3]);
            } else {
                const int third = blockIdx.y >> 2;      // 4 m-tiles of 128 per 512 rows
                const int lr = row & 511;
                hf* d = (third == 0) ? C0 : ((third == 1) ? C1 : C2);
                *reinterpret_cast<uint32_t*>(&d[(long)lr * ldc + col]) =
                    pack2h(acc[i][j][0], acc[i][j][1]);
                *reinterpret_cast<uint32_t*>(&d[(long)(lr + 8) * ldc + col]) =
                    pack2h(acc[i][j][2], acc[i][j][3]);
            }
        }
    }
}

// ============================================================================
// split kernel: fp32 -> half
// ============================================================================
__global__ __launch_bounds__(256) void split_hi(
    const float* __restrict__ s, hf* __restrict__ h, long n)
{
    long i = ((long)blockIdx.x * 256 + threadIdx.x) * 4;
    if (i >= n) return;
    float4 v = *reinterpret_cast<const float4*>(s + i);
    *reinterpret_cast<uint2*>(h + i) = make_uint2(pack2h(v.x, v.y), pack2h(v.z, v.w));
}

// ============================================================================
// softmax over L, in-place on fp16 logits (block owns one full row)
// ============================================================================
__global__ __launch_bounds__(256) void softmax_h(hf* __restrict__ kh)
{
    const int r = blockIdx.x;
    const int b = blockIdx.y;
    const long off = ((long)b * CC + r) * LL;
    hf* p = kh + off;
    const int tid = threadIdx.x;
    __shared__ float red[8];

    float v[16];
    float mx = -1e30f;
    #pragma unroll
    for (int i = 0; i < 16; i++) { v[i] = __half2float(p[tid + i * 256]); mx = fmaxf(mx, v[i]); }
    #pragma unroll
    for (int o = 16; o > 0; o >>= 1) mx = fmaxf(mx, __shfl_xor_sync(0xffffffffu, mx, o));
    if ((tid & 31) == 0) red[tid >> 5] = mx;
    __syncthreads();
    if (tid < 32) {
        float m2 = (tid < 8) ? red[tid] : -1e30f;
        #pragma unroll
        for (int o = 4; o > 0; o >>= 1) m2 = fmaxf(m2, __shfl_xor_sync(0xffffffffu, m2, o));
        if (tid == 0) red[0] = m2;
    }
    __syncthreads();
    mx = red[0];
    __syncthreads();

    float s = 0.0f;
    #pragma unroll
    for (int i = 0; i < 16; i++) { v[i] = __expf(v[i] - mx); s += v[i]; }
    #pragma unroll
    for (int o = 16; o > 0; o >>= 1) s += __shfl_xor_sync(0xffffffffu, s, o);
    if ((tid & 31) == 0) red[tid >> 5] = s;
    __syncthreads();
    if (tid < 32) {
        float s2 = (tid < 8) ? red[tid] : 0.0f;
        #pragma unroll
        for (int o = 4; o > 0; o >>= 1) s2 += __shfl_xor_sync(0xffffffffu, s2, o);
        if (tid == 0) red[0] = s2;
    }
    __syncthreads();
    const float inv = 1.0f / red[0];

    #pragma unroll
    for (int i = 0; i < 16; i++)
        p[tid + i * 256] = __float2half_rn(v[i] * inv);
}

// ============================================================================
extern "C" void kernel_launch(void* const* d_in, const int* in_sizes, int n_in,
                              void* d_out, int out_size)
{
    const float* x = nullptr; const float* w_qkv = nullptr;
    const float* w_out = nullptr; const float* b_out = nullptr;
    for (int i = 0; i < n_in; i++) {
        switch (in_sizes[i]) {
            case 33554432: x     = (const float*)d_in[i]; break;
            case 786432:   w_qkv = (const float*)d_in[i]; break;
            case 262144:   w_out = (const float*)d_in[i]; break;
            case 512:      b_out = (const float*)d_in[i]; break;
            default: break;
        }
    }
    float* y = (float*)d_out;

    hf *xh, *qh, *vh, *kh, *ch, *mh, *wqh, *woh;
    cudaGetSymbolAddress((void**)&xh, g_xh);
    cudaGetSymbolAddress((void**)&qh, g_qh);
    cudaGetSymbolAddress((void**)&vh, g_vh);
    cudaGetSymbolAddress((void**)&kh, g_kh);
    cudaGetSymbolAddress((void**)&ch, g_ch);
    cudaGetSymbolAddress((void**)&mh, g_mh);
    cudaGetSymbolAddress((void**)&wqh, g_wqh);
    cudaGetSymbolAddress((void**)&woh, g_woh);

    cudaFuncSetAttribute(wgemm<true,  2, false>, cudaFuncAttributeMaxDynamicSharedMemorySize, WG_SMEM);
    cudaFuncSetAttribute(wgemm<false, 3, false>, cudaFuncAttributeMaxDynamicSharedMemorySize, WG_SMEM);
    cudaFuncSetAttribute(wgemm<true,  0, true >, cudaFuncAttributeMaxDynamicSharedMemorySize, WG_SMEM);

    const long sBig = (long)CC * LL;
    const long sCtx = (long)CC * CC;

    // 0) pre-split inputs to fp16
    split_hi<<<(unsigned)((size_t)BB * CC * LL / 1024), 256>>>(x, xh, (long)BB * CC * LL);
    split_hi<<<3 * CC * CC / 1024, 256>>>(w_qkv, wqh, 3 * CC * CC);
    split_hi<<<CC * CC / 1024, 256>>>(w_out, woh, CC * CC);

    // 1) qkv = w_qkv @ x (NN): q -> qh, k-logits -> kh, v -> vh (all fp16)
    wgemm<true, 2, false><<<dim3(LL / 128, (3 * CC) / 128, BB), 128, WG_SMEM>>>(
        wqh, xh, nullptr, qh, kh, vh, nullptr,
        CC, 0, sBig, sBig, CC, LL, LL);

    // 2) softmax over L, in-place on kh
    softmax_h<<<dim3(CC, BB), 256>>>(kh);

    // 3) ctx = k_sm @ v^T (NT) -> fp16
    wgemm<false, 3, false><<<dim3(CC / 128, CC / 128, BB), 128, WG_SMEM>>>(
        kh, vh, nullptr, ch, nullptr, nullptr, nullptr,
        LL, sBig, sBig, sCtx, LL, LL, CC);

    // 4) M = w_out @ ctx^T (NT) -> fp16
    wgemm<false, 3, false><<<dim3(CC / 128, CC / 128, BB), 128, WG_SMEM>>>(
        woh, ch, nullptr, mh, nullptr, nullptr, nullptr,
        CC, 0, sCtx, sCtx, CC, CC, CC);

    // 5) y = M @ q + b_out (NN, fp32 + bias)
    wgemm<true, 0, true><<<dim3(LL / 128, CC / 128, BB), 128, WG_SMEM>>>(
        mh, qh, y, nullptr, nullptr, nullptr, b_out,
        CC, sCtx, sBig, sBig, CC, LL, LL);

    (void)out_size;
}